// round 16
// baseline (speedup 1.0000x reference)
#include <cuda_runtime.h>
#include <cstdint>

// Problem constants
#define NN 32
#define TT 1024
#define EE 64
#define HH 8
#define DD 8

// Attention tiling
#define A_THREADS 128
#define QPT 2                         // q rows per thread (one packed pair)
#define QROWS (A_THREADS * QPT)       // 256
#define QSPLIT (TT / QROWS)           // 4
#define KCHUNK 256                    // keys per smem stage

#define LOG2E 1.4426950408889634f
#define QSCALE (0.125f * LOG2E)       // 1/sqrt(64) * log2(e), folded into q
#define CLIPV (5.0f * LOG2E)          // clip(energy*scale, ±5) in log2 domain

// Device scratch (allocation-free)
__device__ float g_q [(size_t)NN * HH * TT * DD];       // prescaled Q [n,h,t,d]
__device__ float g_kd[(size_t)NN * HH * TT * DD * 2];   // K dup: (k_d,k_d) pairs
__device__ float g_vd[(size_t)NN * HH * TT * DD * 2];   // V dup: (v_d,v_d) pairs
__device__ float g_heads[(size_t)NN * TT * EE];         // attention out [n,t,e]

typedef unsigned long long u64;

// ---- packed f32x2 helpers ----
__device__ __forceinline__ u64 fma2(u64 a, u64 b, u64 c) {
    u64 d; asm("fma.rn.f32x2 %0, %1, %2, %3;" : "=l"(d) : "l"(a), "l"(b), "l"(c));
    return d;
}
__device__ __forceinline__ u64 mul2(u64 a, u64 b) {
    u64 d; asm("mul.rn.f32x2 %0, %1, %2;" : "=l"(d) : "l"(a), "l"(b));
    return d;
}
__device__ __forceinline__ u64 add2(u64 a, u64 b) {
    u64 d; asm("add.rn.f32x2 %0, %1, %2;" : "=l"(d) : "l"(a), "l"(b));
    return d;
}
__device__ __forceinline__ u64 pack2(float lo, float hi) {
    u64 d; asm("mov.b64 %0, {%1, %2};" : "=l"(d)
               : "r"(__float_as_uint(lo)), "r"(__float_as_uint(hi)));
    return d;
}
__device__ __forceinline__ void unpack2(u64 a, float& lo, float& hi) {
    unsigned int l, h;
    asm("mov.b64 {%0, %1}, %2;" : "=r"(l), "=r"(h) : "l"(a));
    lo = __uint_as_float(l); hi = __uint_as_float(h);
}
__device__ __forceinline__ float ex2f(float x) {
    float r; asm("ex2.approx.ftz.f32 %0, %1;" : "=f"(r) : "f"(x));
    return r;
}

// ============================================================================
// Kernel 0: QKV projection. thread = (token, head), h fastest (coalesced).
// Q pre-scaled by QSCALE (score lands in log2 domain).
// K/V written in per-(n,h) [t,d] layout, each element DUPLICATED (x,x) so the
// attention mainloop can run row-pair-packed f32x2 math with no hadd.
// ============================================================================
__global__ void __launch_bounds__(256)
qkv_kernel(const float* __restrict__ values,
           const float* __restrict__ keys,
           const float* __restrict__ query,
           const float* __restrict__ Wv,
           const float* __restrict__ Wk,
           const float* __restrict__ Wq)
{
    __shared__ float sWv[64], sWk[64], sWq[64];
    const int tid = threadIdx.x;
    if (tid < 64) { sWv[tid] = Wv[tid]; sWk[tid] = Wk[tid]; sWq[tid] = Wq[tid]; }
    __syncthreads();

    const int id  = blockIdx.x * 256 + tid;
    const int tok = id >> 3;
    const int h   = id & 7;
    const int n   = tok >> 10;
    const int t   = tok & 1023;
    const size_t src  = (size_t)tok * EE + h * DD;
    const size_t dst  = ((size_t)(n * HH + h) * TT + t) * DD;      // q
    const size_t dstd = dst * 2;                                   // dup k/v

    float in[8], pr[8];

    // Q (pre-scaled)
    {
        float4 a = *(const float4*)(query + src);
        float4 b = *(const float4*)(query + src + 4);
        in[0]=a.x; in[1]=a.y; in[2]=a.z; in[3]=a.w;
        in[4]=b.x; in[5]=b.y; in[6]=b.z; in[7]=b.w;
#pragma unroll
        for (int o = 0; o < 8; o++) {
            float s = 0.f;
#pragma unroll
            for (int i = 0; i < 8; i++) s += in[i] * sWq[o * 8 + i];
            pr[o] = s * QSCALE;
        }
        *(float4*)(g_q + dst)     = make_float4(pr[0], pr[1], pr[2], pr[3]);
        *(float4*)(g_q + dst + 4) = make_float4(pr[4], pr[5], pr[6], pr[7]);
    }
    // K (duplicated)
    {
        float4 a = *(const float4*)(keys + src);
        float4 b = *(const float4*)(keys + src + 4);
        in[0]=a.x; in[1]=a.y; in[2]=a.z; in[3]=a.w;
        in[4]=b.x; in[5]=b.y; in[6]=b.z; in[7]=b.w;
#pragma unroll
        for (int o = 0; o < 8; o++) {
            float s = 0.f;
#pragma unroll
            for (int i = 0; i < 8; i++) s += in[i] * sWk[o * 8 + i];
            pr[o] = s;
        }
#pragma unroll
        for (int p = 0; p < 4; p++)
            *(float4*)(g_kd + dstd + p * 4) =
                make_float4(pr[2*p], pr[2*p], pr[2*p+1], pr[2*p+1]);
    }
    // V (duplicated)
    {
        float4 a = *(const float4*)(values + src);
        float4 b = *(const float4*)(values + src + 4);
        in[0]=a.x; in[1]=a.y; in[2]=a.z; in[3]=a.w;
        in[4]=b.x; in[5]=b.y; in[6]=b.z; in[7]=b.w;
#pragma unroll
        for (int o = 0; o < 8; o++) {
            float s = 0.f;
#pragma unroll
            for (int i = 0; i < 8; i++) s += in[i] * sWv[o * 8 + i];
            pr[o] = s;
        }
#pragma unroll
        for (int p = 0; p < 4; p++)
            *(float4*)(g_vd + dstd + p * 4) =
                make_float4(pr[2*p], pr[2*p], pr[2*p+1], pr[2*p+1]);
    }
}

// ============================================================================
// Kernel A: row-pair-packed single-pass softmax attention.
// Each thread owns q rows r0, r1=r0+128 packed as (r0,r1) in f32x2 lanes.
// K/V are duplicated per-dim in smem, so:
//   8 fma2  -> both dots (no horizontal add)
//   1 add2  -> both esums
//   8 fma2  -> both AV accumulations
// exp = raw ex2 after clip at +-5*log2e (q was prescaled by scale*log2e).
// grid = (QSPLIT=4, H, N) = 1024 CTAs, 128 thr -> ~7 CTAs/SM, single wave.
// ============================================================================
__global__ void __launch_bounds__(A_THREADS)
attn_kernel()
{
    __shared__ __align__(16) float sK[KCHUNK * 16];  // 16 KB (dup)
    __shared__ __align__(16) float sV[KCHUNK * 16];  // 16 KB (dup)

    const int tid = threadIdx.x;
    const int qs  = blockIdx.x;
    const int h   = blockIdx.y;
    const int n   = blockIdx.z;

    const size_t rowbase = (size_t)(n * HH + h) * TT;

    const int r0 = qs * QROWS + tid;
    const int r1 = r0 + A_THREADS;

    // pack q rows r0/r1 per-dim
    u64 qp[8];
    {
        const float* q0 = g_q + (rowbase + r0) * DD;
        const float* q1 = g_q + (rowbase + r1) * DD;
        float4 a0 = *(const float4*)(q0), b0 = *(const float4*)(q0 + 4);
        float4 a1 = *(const float4*)(q1), b1 = *(const float4*)(q1 + 4);
        qp[0] = pack2(a0.x, a1.x); qp[1] = pack2(a0.y, a1.y);
        qp[2] = pack2(a0.z, a1.z); qp[3] = pack2(a0.w, a1.w);
        qp[4] = pack2(b0.x, b1.x); qp[5] = pack2(b0.y, b1.y);
        qp[6] = pack2(b0.z, b1.z); qp[7] = pack2(b0.w, b1.w);
    }

    u64 acc[8];
#pragma unroll
    for (int d = 0; d < 8; d++) acc[d] = 0ull;
    u64 esum2 = 0ull;

    for (int kc = 0; kc < TT; kc += KCHUNK) {
        // bulk copy dup K/V chunk (contiguous, coalesced)
        const float4* kb = (const float4*)(g_kd + (rowbase + kc) * 16);
        const float4* vb = (const float4*)(g_vd + (rowbase + kc) * 16);
#pragma unroll
        for (int t = 0; t < (KCHUNK * 16 / 4) / A_THREADS; t++) {
            const int idx = t * A_THREADS + tid;
            ((float4*)sK)[idx] = kb[idx];
            ((float4*)sV)[idx] = vb[idx];
        }
        __syncthreads();

#pragma unroll 2
        for (int j = 0; j < KCHUNK; j++) {
            const ulonglong2* kp = (const ulonglong2*)(sK + j * 16);
            const ulonglong2* vp = (const ulonglong2*)(sV + j * 16);
            const ulonglong2 k01 = kp[0], k23 = kp[1], k45 = kp[2], k67 = kp[3];

            u64 s2 = mul2(qp[0], k01.x);
            s2 = fma2(qp[1], k01.y, s2);
            s2 = fma2(qp[2], k23.x, s2);
            s2 = fma2(qp[3], k23.y, s2);
            s2 = fma2(qp[4], k45.x, s2);
            s2 = fma2(qp[5], k45.y, s2);
            s2 = fma2(qp[6], k67.x, s2);
            s2 = fma2(qp[7], k67.y, s2);

            float s0, s1;
            unpack2(s2, s0, s1);
            s0 = fminf(fmaxf(s0, -CLIPV), CLIPV);
            s1 = fminf(fmaxf(s1, -CLIPV), CLIPV);
            const float e0 = ex2f(s0);
            const float e1 = ex2f(s1);
            const u64 e2 = pack2(e0, e1);
            esum2 = add2(esum2, e2);

            const ulonglong2 v01 = vp[0], v23 = vp[1], v45 = vp[2], v67 = vp[3];
            acc[0] = fma2(e2, v01.x, acc[0]);
            acc[1] = fma2(e2, v01.y, acc[1]);
            acc[2] = fma2(e2, v23.x, acc[2]);
            acc[3] = fma2(e2, v23.y, acc[3]);
            acc[4] = fma2(e2, v45.x, acc[4]);
            acc[5] = fma2(e2, v45.y, acc[5]);
            acc[6] = fma2(e2, v67.x, acc[6]);
            acc[7] = fma2(e2, v67.y, acc[7]);
        }
        __syncthreads();
    }

    // normalize + write both rows into g_heads [n,t,e]
    float es0, es1;
    unpack2(esum2, es0, es1);
    const float inv0 = 1.f / es0;
    const float inv1 = 1.f / es1;

    float o0[8], o1[8];
#pragma unroll
    for (int d = 0; d < 8; d++) {
        float lo, hi;
        unpack2(acc[d], lo, hi);
        o0[d] = lo * inv0;
        o1[d] = hi * inv1;
    }
    {
        float* dst = g_heads + ((size_t)(n * TT + r0)) * EE + h * DD;
        *(float4*)(dst)     = make_float4(o0[0], o0[1], o0[2], o0[3]);
        *(float4*)(dst + 4) = make_float4(o0[4], o0[5], o0[6], o0[7]);
    }
    {
        float* dst = g_heads + ((size_t)(n * TT + r1)) * EE + h * DD;
        *(float4*)(dst)     = make_float4(o1[0], o1[1], o1[2], o1[3]);
        *(float4*)(dst + 4) = make_float4(o1[4], o1[5], o1[6], o1[7]);
    }
}

// ============================================================================
// Kernel B: out = heads @ Wo^T + bo, Wo held entirely in registers per lane
// (rows o=lane, o=lane+32). x broadcast from per-warp smem.
// ============================================================================
#define PB_WARPS 8
#define PB_TOKS 8
#define PB_BLOCK (PB_WARPS * 32)

__global__ void __launch_bounds__(PB_BLOCK)
out_kernel(const float* __restrict__ Wo,
           const float* __restrict__ bo,
           float* __restrict__ out)
{
    __shared__ float sW[64 * 65];
    __shared__ float sx[PB_WARPS][64];
    __shared__ float sb[64];

    const int tid  = threadIdx.x;
    const int lane = tid & 31;
    const int warp = tid >> 5;

    for (int idx = tid; idx < 64 * 64; idx += PB_BLOCK) {
        int o = idx >> 6, i = idx & 63;
        sW[o * 65 + i] = Wo[idx];
    }
    if (tid < 64) sb[tid] = bo[tid];
    __syncthreads();

    float Wr0[64], Wr1[64];
#pragma unroll
    for (int i = 0; i < 64; i++) {
        Wr0[i] = sW[lane * 65 + i];
        Wr1[i] = sW[(lane + 32) * 65 + i];
    }
    const float b0 = sb[lane], b1 = sb[lane + 32];

    const int tok0 = blockIdx.x * (PB_WARPS * PB_TOKS) + warp * PB_TOKS;
    float* sxw = sx[warp];

    for (int t = 0; t < PB_TOKS; t++) {
        const int tok = tok0 + t;
        const float2 xv =
            *reinterpret_cast<const float2*>(g_heads + (size_t)tok * 64 + lane * 2);
        __syncwarp();
        *reinterpret_cast<float2*>(sxw + lane * 2) = xv;
        __syncwarp();

        float a0 = b0, a1 = b1, c0 = 0.f, c1 = 0.f;
#pragma unroll
        for (int i = 0; i < 64; i += 2) {
            const float x0 = sxw[i], x1 = sxw[i + 1];
            a0 += x0 * Wr0[i];     a1 += x0 * Wr1[i];
            c0 += x1 * Wr0[i + 1]; c1 += x1 * Wr1[i + 1];
        }
        out[(size_t)tok * 64 + lane]      = a0 + c0;
        out[(size_t)tok * 64 + 32 + lane] = a1 + c1;
    }
}

// ============================================================================
// Launch
// ============================================================================
extern "C" void kernel_launch(void* const* d_in, const int* in_sizes, int n_in,
                              void* d_out, int out_size)
{
    const float* values = (const float*)d_in[0];
    const float* keys   = (const float*)d_in[1];
    const float* query  = (const float*)d_in[2];
    const float* Wv     = (const float*)d_in[3];
    const float* Wk     = (const float*)d_in[4];
    const float* Wq     = (const float*)d_in[5];
    const float* Wo     = (const float*)d_in[6];
    const float* bo     = (const float*)d_in[7];
    float* out = (float*)d_out;

    qkv_kernel<<<(NN * TT * HH) / 256, 256>>>(values, keys, query, Wv, Wk, Wq);

    dim3 gridA(QSPLIT, HH, NN);  // (4, 8, 32) = 1024 CTAs
    attn_kernel<<<gridA, A_THREADS>>>();

    const int n_tokens = NN * TT;
    out_kernel<<<n_tokens / (PB_WARPS * PB_TOKS), PB_BLOCK>>>(Wo, bo, out);
}